// round 17
// baseline (speedup 1.0000x reference)
#include <cuda_runtime.h>
#include <stdint.h>

#define X_COORD_START 10
#define Y_COORD_START 21
#define EOS_TOKEN     39
#define MAX_REACH     5.0f
#define WINDOW_SIZE   4
#define PENALTY_SCALE 1.0f

#define ROW_LEN      2048   // tokens per row
#define ROWS_PER_CTA 2      // processed CONCURRENTLY by two warp groups
#define NTHREADS     256    // 8 warps: warps 0-3 = row A, warps 4-7 = row B
#define WCHUNKS      4      // int4 chunks per warp
#define WSEGCAP      256
#define NBUCKETS     64
#define BSTRIDE      32     // doubles: 256B apart
#define ISTRIDE      64     // ints: 256B apart

// SIMD validity constants: bytes (x_lo, y_lo, x_lo, y_lo) and range widths
#define SUB_CONST 0x150A150Au   // bytes: 10,21,10,21
#define RNG_CONST 0x120B120Bu   // bytes: 11,18,11,18

// Bucketed self-resetting scratch (zeroed at load; last CTA resets per launch).
__device__ double        g_bt[NBUCKETS * BSTRIDE];
__device__ int           g_bn[NBUCKETS * ISTRIDE];
__device__ unsigned int  g_counter = 0;

__device__ __forceinline__ void rowbar(int id) {
    asm volatile("bar.sync %0, 128;" :: "r"(id) : "memory");
}

__global__ __launch_bounds__(NTHREADS, 6)
void reach_loss_v17(const int* __restrict__ in, float* __restrict__ out,
                    int n_ctas) {
    const int t    = threadIdx.x;
    const int lane = t & 31;
    const int wid  = t >> 5;           // 0..7
    const int rh   = wid >> 2;         // row group: 0 or 1
    const int rt   = t & 127;          // thread index within row group
    const unsigned lt = (1u << lane) - 1u;
    const int barid = 1 + rh;          // named barrier per row group

    __shared__ unsigned short wseg[8][WSEGCAP];   // per-warp compaction
    __shared__ unsigned short rowbuf[2][1028];    // contiguous per row
    __shared__ int    scnt[8];
    __shared__ float  wpart[8];
    __shared__ float  s_acc[2];
    __shared__ int    s_nv[2];
    __shared__ int    s_last;
    __shared__ double s_red[2];
    __shared__ float  s_cnt[2];

    const int* rowp = in + (size_t)(blockIdx.x * ROWS_PER_CTA + rh) * ROW_LEN;

    // ---- Load this warp's quarter row: 4 independent LDG.128 ----
    int4 v[WCHUNKS];
    #pragma unroll
    for (int c = 0; c < WCHUNKS; c++)
        v[c] = reinterpret_cast<const int4*>(rowp)
                   [((wid & 3) * WCHUNKS + c) * 32 + lane];

    // ---- SIMD single-pass ballot compaction into warp-private segment ----
    // int4 q holds pair A = 2q-1 (tokens 4q,4q+1; q>=1) and pair B = 2q.
    int cnt = 0;
    #pragma unroll
    for (int c = 0; c < WCHUNKS; c++) {
        const int4 p = v[c];
        const int q = ((wid & 3) * WCHUNKS + c) * 32 + lane;
        const unsigned pk = __byte_perm(__byte_perm(p.x, p.y, 0x0040),
                                        __byte_perm(p.z, p.w, 0x0040),
                                        0x5410);
        const unsigned d  = __vsub4(pk, SUB_CONST);   // (x-10, y-21, ...)
        const unsigned m  = __vcmpltu4(d, RNG_CONST); // 0xff per in-range byte
        const bool va = ((m & 0xffffu) == 0xffffu) && (q != 0);
        const bool vb = (m >> 16) == 0xffffu;
        const unsigned bA = __ballot_sync(0xffffffffu, va);
        const unsigned bB = __ballot_sync(0xffffffffu, vb);
        const int pos = cnt + __popc(bA & lt) + __popc(bB & lt);
        if (va) wseg[wid][pos]            = (unsigned short)((d & 0xffffu) + 0x0100u);
        if (vb) wseg[wid][pos + (va?1:0)] = (unsigned short)((d >> 16) + 0x0100u);
        cnt += __popc(bA) + __popc(bB);
    }
    if (lane == 0) scnt[wid] = cnt;
    rowbar(barid);   // row group's segments + counts visible

    const int b0 = rh * 4;
    const int s0 = scnt[b0], s1 = scnt[b0+1], s2 = scnt[b0+2], s3 = scnt[b0+3];
    const int p1 = s0, p2 = s0 + s1, p3 = s0 + s1 + s2;
    const int total = p3 + s3;

    // ---- Merge 4 segments into this row's contiguous buffer ----
    unsigned short* buf = rowbuf[rh];
    for (int i = rt; i < total; i += 128) {
        const int w = (i >= p1) + (i >= p2) + (i >= p3);
        const int base = (w == 0) ? 0 : (w == 1) ? p1 : (w == 2) ? p2 : p3;
        buf[i] = wseg[b0 + w][i - base];
    }
    rowbar(barid);   // row buffer complete

    // ---- Balanced window loop: SIMD byte distances + approx sqrt ----
    float vsum = 0.0f;
    for (int i = WINDOW_SIZE + rt; i < total; i += 128) {
        const int ci = (int)buf[i];
        int msq = 0x7fffffff;
        #pragma unroll
        for (int j = 1; j <= WINDOW_SIZE; j++) {
            const int cj = (int)buf[i - j];
            const int d  = __vsub4(ci, cj);
            msq = min(msq, __dp4a(d, d, 0));
        }
        float sd;
        asm("sqrt.approx.f32 %0, %1;" : "=f"(sd) : "f"((float)msq));
        vsum += fmaxf(sd - MAX_REACH, 0.0f);   // exact 0 when msq <= 25
    }
    #pragma unroll
    for (int o = 16; o > 0; o >>= 1)
        vsum += __shfl_xor_sync(0xffffffffu, vsum, o);
    if (lane == 0) wpart[wid] = vsum;
    rowbar(barid);   // row group's partials visible

    if (rt == 0) {
        if (total >= WINDOW_SIZE + 1) {
            const float pen = wpart[b0] + wpart[b0+1] + wpart[b0+2] + wpart[b0+3];
            s_acc[rh] = pen / (float)(total - WINDOW_SIZE);
            s_nv[rh]  = 1;
        } else {
            s_acc[rh] = 0.0f;
            s_nv[rh]  = 0;
        }
    }
    __syncthreads();   // both rows done

    // ---- Bucketed fire-and-forget accumulation + single ticket ----
    if (t == 0) {
        const int b = blockIdx.x & (NBUCKETS - 1);
        const float acc = s_acc[0] + s_acc[1];
        const int   nvs = s_nv[0] + s_nv[1];
        if (nvs) {
            atomicAdd(&g_bt[b * BSTRIDE], (double)acc);  // RED
            atomicAdd(&g_bn[b * ISTRIDE], nvs);          // RED
        }
        __threadfence();
        const unsigned ticket = atomicAdd(&g_counter, 1u);
        s_last = (ticket == (unsigned)(n_ctas - 1)) ? 1 : 0;
    }
    __syncthreads();

    // ---- Parallel finalize + reset by the last CTA ----
    if (s_last) {
        double bt = 0.0;
        int    bn = 0;
        if (t < NBUCKETS) {
            bt = *((volatile double*)&g_bt[t * BSTRIDE]);
            bn = *((volatile int*)&g_bn[t * ISTRIDE]);
            g_bt[t * BSTRIDE] = 0.0;
            g_bn[t * ISTRIDE] = 0;
        }
        #pragma unroll
        for (int o = 16; o > 0; o >>= 1) {
            bt += __shfl_xor_sync(0xffffffffu, bt, o);
            bn += __shfl_xor_sync(0xffffffffu, bn, o);
        }
        if (t == 0)  { s_red[0] = bt; s_cnt[0] = (float)bn; }
        if (t == 32) { s_red[1] = bt; s_cnt[1] = (float)bn; }
        __syncthreads();
        if (t == 0) {
            const double tot = s_red[0] + s_red[1];
            const int    tn  = (int)s_cnt[0] + (int)s_cnt[1];
            out[0] = (tn > 0) ? (float)(PENALTY_SCALE * tot / (double)tn) : 0.0f;
            __threadfence();
            g_counter = 0u;
        }
    }
}

extern "C" void kernel_launch(void* const* d_in, const int* in_sizes, int n_in,
                              void* d_out, int out_size) {
    (void)n_in; (void)out_size;
    const int* in = (const int*)d_in[0];
    const int B = in_sizes[0] / ROW_LEN;            // 2048 rows
    const int n_ctas = B / ROWS_PER_CTA;            // 1024 CTAs
    reach_loss_v17<<<n_ctas, NTHREADS>>>(in, (float*)d_out, n_ctas);
}